// round 5
// baseline (speedup 1.0000x reference)
#include <cuda_runtime.h>

#define T_LEN 1024
#define BATCH 4
#define EMB   1024
#define NH    16
#define HD    64
#define BH    (BATCH*NH)   // 64
#define NREL  33           // 2L+1

// k-dim permutation within each 8-group: {0,1,2,3,4,5,6,7} -> positions
// {0,2,4,6,1,3,5,7}, so (k, k+4) land adjacent -> LDS.64 fragment loads.
__device__ __forceinline__ int perm8(int x) {
    return (x & ~7) | ((x & 3) << 1) | ((x >> 2) & 1);
}

// Scratch (static device arrays: allocation-free per harness rules)
__device__ float g_q[BH * T_LEN * HD];        // tf32 bits, [bh][t][perm(d)], q pre-scaled
__device__ float g_k[BH * T_LEN * HD];        // tf32 bits, [bh][t][perm(d)]
__device__ float g_v[BH * HD * T_LEN];        // tf32 bits, TRANSPOSED [bh][d][perm(t)]
__device__ float g_attn[T_LEN * BATCH * EMB]; // tf32 bits, [t*4+b][perm(e)]
__device__ float g_qin[4096 * 1024];          // tf32(query), k-permuted
__device__ float g_win[3072 * 1024];          // tf32(w_in),  k-permuted
__device__ float g_wout[1024 * 1024];         // tf32(w_out), k-permuted

__device__ __forceinline__ unsigned f2tf(float f) {
    unsigned u;
    asm("cvt.rna.tf32.f32 %0, %1;" : "=r"(u) : "f"(f));
    return u;
}

// D += A @ B  (m16n8k8, tf32 in, fp32 accum). c aliases d.
__device__ __forceinline__ void mma8(float* c, const unsigned* a, const unsigned* b) {
    asm volatile(
        "mma.sync.aligned.m16n8k8.row.col.f32.tf32.tf32.f32 "
        "{%0,%1,%2,%3}, {%4,%5,%6,%7}, {%8,%9}, {%0,%1,%2,%3};\n"
        : "+f"(c[0]), "+f"(c[1]), "+f"(c[2]), "+f"(c[3])
        : "r"(a[0]), "r"(a[1]), "r"(a[2]), "r"(a[3]), "r"(b[0]), "r"(b[1]));
}

// ---------------------------------------------------------------------------
// fp32 -> tf32(rna), k-permuted within 8-groups. One thread = one 8-group.
// Fully coalesced loads and stores (permute happens in registers).
// ---------------------------------------------------------------------------
__global__ void __launch_bounds__(256)
cvt_tf32p(const float* __restrict__ in, float* __restrict__ out_, int n8)
{
    const int i = blockIdx.x * 256 + threadIdx.x;
    if (i < n8) {
        float4 v0 = ((const float4*)in)[2 * i];
        float4 v1 = ((const float4*)in)[2 * i + 1];
        uint4 a = make_uint4(f2tf(v0.x), f2tf(v1.x), f2tf(v0.y), f2tf(v1.y));
        uint4 b = make_uint4(f2tf(v0.z), f2tf(v1.z), f2tf(v0.w), f2tf(v1.w));
        ((uint4*)out_)[2 * i]     = a;
        ((uint4*)out_)[2 * i + 1] = b;
    }
}

// ---------------------------------------------------------------------------
// TC GEMM: C[M,N] = A[M,K] * B[N,K]^T + bias[N].  A,B = tf32 bits, k-permuted.
// mode 0: scatter tf32 q/k/v (q scaled, v transposed). mode 1: fp32 Cout.
// Block 128x128, K-chunk 32, 8 warps, 2-stage smem pipeline, 2 CTAs/SM.
// All smem fills are verbatim STS.128; all fragment loads are LDS.64.
// ---------------------------------------------------------------------------
#define GSTG (128 * 36)

__global__ void __launch_bounds__(256, 2)
gemm_tc(const float* __restrict__ A, const float* __restrict__ B,
        const float* __restrict__ bias, float* __restrict__ Cout,
        int M, int N, int K, int mode)
{
    extern __shared__ unsigned sh[];
    unsigned* As = sh;               // [2][128*36], stride 36 (≡4 mod 32)
    unsigned* Bs = sh + 2 * GSTG;

    const int tid  = threadIdx.x;
    const int lane = tid & 31;
    const int warp = tid >> 5;
    const int q4   = lane & 3;          // quad index
    const int g8   = lane >> 2;         // group index 0..7
    const int wm   = (warp & 3) * 32;
    const int wn   = (warp >> 2) * 64;
    const int row0 = blockIdx.y * 128;
    const int col0 = blockIdx.x * 128;

    const int lr = tid >> 3;            // 0..31
    const int lk = (tid & 7) * 4;       // 0..28

    float acc[2][8][4];
#pragma unroll
    for (int mt = 0; mt < 2; mt++)
#pragma unroll
        for (int nt = 0; nt < 8; nt++)
#pragma unroll
            for (int f = 0; f < 4; f++) acc[mt][nt][f] = 0.0f;

    const unsigned* aP = (const unsigned*)A + (size_t)row0 * K;
    const unsigned* bP = (const unsigned*)B + (size_t)col0 * K;

    uint4 pa[4], pb[4];
#pragma unroll
    for (int r = 0; r < 4; r++) {
        pa[r] = *(const uint4*)(aP + (size_t)(lr + 32 * r) * K + lk);
        pb[r] = *(const uint4*)(bP + (size_t)(lr + 32 * r) * K + lk);
    }
#pragma unroll
    for (int r = 0; r < 4; r++) {
        *(uint4*)&As[(lr + 32 * r) * 36 + lk] = pa[r];
        *(uint4*)&Bs[(lr + 32 * r) * 36 + lk] = pb[r];
    }
    __syncthreads();

    const int nC = K >> 5;
    for (int c = 0; c < nC; c++) {
        unsigned* Ac = As + (c & 1) * GSTG;
        unsigned* Bc = Bs + (c & 1) * GSTG;
        unsigned* An = As + ((c & 1) ^ 1) * GSTG;
        unsigned* Bn = Bs + ((c & 1) ^ 1) * GSTG;

        const bool more = (c + 1 < nC);
        if (more) {
            const int ko = (c + 1) * 32 + lk;
#pragma unroll
            for (int r = 0; r < 4; r++) {
                pa[r] = *(const uint4*)(aP + (size_t)(lr + 32 * r) * K + ko);
                pb[r] = *(const uint4*)(bP + (size_t)(lr + 32 * r) * K + ko);
            }
        }

#pragma unroll
        for (int ks = 0; ks < 4; ks++) {
            const int kp = ks * 8 + q4 * 2;      // permuted pair offset
            unsigned a[2][4];
#pragma unroll
            for (int mt = 0; mt < 2; mt++) {
                const int m = wm + mt * 16 + g8;
                uint2 u0 = *(const uint2*)&Ac[m * 36 + kp];
                uint2 u1 = *(const uint2*)&Ac[(m + 8) * 36 + kp];
                a[mt][0] = u0.x; a[mt][1] = u1.x;
                a[mt][2] = u0.y; a[mt][3] = u1.y;
            }
#pragma unroll
            for (int nt = 0; nt < 8; nt++) {
                const int n = wn + nt * 8 + g8;
                uint2 ub = *(const uint2*)&Bc[n * 36 + kp];
                unsigned b[2] = {ub.x, ub.y};
                mma8(acc[0][nt], a[0], b);
                mma8(acc[1][nt], a[1], b);
            }
        }

        if (more) {
#pragma unroll
            for (int r = 0; r < 4; r++) {
                *(uint4*)&An[(lr + 32 * r) * 36 + lk] = pa[r];
                *(uint4*)&Bn[(lr + 32 * r) * 36 + lk] = pb[r];
            }
        }
        __syncthreads();
    }

    // epilogue
#pragma unroll
    for (int mt = 0; mt < 2; mt++) {
#pragma unroll
        for (int rr = 0; rr < 2; rr++) {
            const int m = row0 + wm + mt * 16 + g8 + rr * 8;
#pragma unroll
            for (int nt = 0; nt < 8; nt++) {
#pragma unroll
                for (int cc = 0; cc < 2; cc++) {
                    const int n = col0 + wn + nt * 8 + 2 * q4 + cc;
                    float v = acc[mt][nt][rr * 2 + cc] + bias[n];
                    if (mode == 0) {
                        const int sec = n >> 10;       // 0=q 1=k 2=v
                        const int e = n & 1023;
                        const int h = e >> 6, d = e & 63;
                        const int t = m >> 2, b = m & 3;
                        const int bh = b * NH + h;
                        if (sec == 0)
                            g_q[(bh * T_LEN + t) * HD + perm8(d)] =
                                __uint_as_float(f2tf(v * 0.125f));
                        else if (sec == 1)
                            g_k[(bh * T_LEN + t) * HD + perm8(d)] =
                                __uint_as_float(f2tf(v));
                        else
                            g_v[((size_t)bh * HD + d) * T_LEN + perm8(t)] =
                                __uint_as_float(f2tf(v));
                    } else {
                        Cout[(size_t)m * N + n] = v;
                    }
                }
            }
        }
    }
}

// ---------------------------------------------------------------------------
// Flash attention with Shaw relative bias, tensor-core QK^T and PV.
// grid = (16 q-tiles of 64, 64 heads), 128 threads (4 warps, 16 q-rows each).
// Inputs tf32 + k-permuted -> verbatim tile copies, LDS.64 fragment loads.
// ---------------------------------------------------------------------------
__global__ void __launch_bounds__(128)
attn_tc(const float* __restrict__ relk)
{
    extern __shared__ float sm[];
    unsigned* Qs = (unsigned*)sm;             // [64][68]  (perm d)
    unsigned* Ks = Qs + 64 * 68;              // [64][68]  (perm d)
    unsigned* Vs = Ks + 64 * 68;              // [64][68]  rows=d, cols=perm(s)
    unsigned* Ps = Vs + 64 * 68;              // [64][68]  (perm c)
    float* rels  = (float*)(Ps + 64 * 68);    // [33][68]  (perm d)
    float* qrs   = rels + 33 * 68;            // [64][33]

    const int tid  = threadIdx.x;
    const int lane = tid & 31;
    const int warp = tid >> 5;                // 0..3
    const int q4   = lane & 3;
    const int g8   = lane >> 2;               // 0..7
    const int bh   = blockIdx.y;
    const int tq0  = blockIdx.x * 64;
    const int m0   = warp * 16;

    // load Q tile (64x64, tf32, perm'd) — verbatim
    {
        const uint4* qb = (const uint4*)(g_q + (size_t)(bh * T_LEN + tq0) * HD);
#pragma unroll 2
        for (int i = tid; i < 1024; i += 128)
            *(uint4*)&Qs[(i >> 4) * 68 + (i & 15) * 4] = qb[i];
    }
    // relation keys: first 64 channels, stored at perm'd position
    for (int i = tid; i < NREL * 64; i += 128) {
        const int j = i >> 6, d = i & 63;
        rels[j * 68 + perm8(d)] = relk[j * EMB + d];
    }
    __syncthreads();

    // qr[r][j] = q[r] . rel[j]  (both perm'd identically; sum order free)
    for (int e = tid; e < 64 * NREL; e += 128) {
        const int r = e / NREL, j = e - r * NREL;
        const float* qp = (const float*)&Qs[r * 68];
        const float* rp = &rels[j * 68];
        float s = 0.0f;
#pragma unroll
        for (int d = 0; d < 64; d++) s = fmaf(qp[d], rp[d], s);
        qrs[r * NREL + j] = s;
    }

    const float* kbase = g_k + (size_t)bh * T_LEN * HD;   // [t][perm d]
    const float* vbase = g_v + (size_t)bh * HD * T_LEN;   // [d][perm t]

    // prefetch tile 0
    uint4 pk[8], pv[8];
#pragma unroll
    for (int it = 0; it < 8; it++) {
        const int i = tid + 128 * it;
        const int r = i >> 4, off = (i & 15) * 4;
        pk[it] = *(const uint4*)(kbase + (size_t)r * HD + off);
        pv[it] = *(const uint4*)(vbase + (size_t)r * T_LEN + off);
    }

    float o[8][4];
#pragma unroll
    for (int nt = 0; nt < 8; nt++)
#pragma unroll
        for (int f = 0; f < 4; f++) o[nt][f] = 0.0f;
    float mrow[2] = {-1e30f, -1e30f};
    float lrow[2] = {0.0f, 0.0f};

    __syncthreads();   // qrs visible

    for (int kt = 0; kt < 16; kt++) {
        const int s0 = kt * 64;

        // store prefetched tile
#pragma unroll
        for (int it = 0; it < 8; it++) {
            const int i = tid + 128 * it;
            const int r = i >> 4, d4 = (i & 15) * 4;
            *(uint4*)&Ks[r * 68 + d4] = pk[it];
            *(uint4*)&Vs[r * 68 + d4] = pv[it];
        }
        __syncthreads();

        // prefetch next tile
        if (kt + 1 < 16) {
#pragma unroll
            for (int it = 0; it < 8; it++) {
                const int i = tid + 128 * it;
                const int r = i >> 4, off = (i & 15) * 4;
                pk[it] = *(const uint4*)(kbase + (size_t)(s0 + 64 + r) * HD + off);
                pv[it] = *(const uint4*)(vbase + (size_t)r * T_LEN + s0 + 64 + off);
            }
        }

        // S = Q @ K^T
        float s[8][4];
#pragma unroll
        for (int nt = 0; nt < 8; nt++)
#pragma unroll
            for (int f = 0; f < 4; f++) s[nt][f] = 0.0f;

#pragma unroll
        for (int ks = 0; ks < 8; ks++) {
            const int kp = ks * 8 + q4 * 2;
            unsigned a[4];
            const int mr = m0 + g8;
            uint2 u0 = *(const uint2*)&Qs[mr * 68 + kp];
            uint2 u1 = *(const uint2*)&Qs[(mr + 8) * 68 + kp];
            a[0] = u0.x; a[1] = u1.x; a[2] = u0.y; a[3] = u1.y;
#pragma unroll
            for (int nt = 0; nt < 8; nt++) {
                uint2 ub = *(const uint2*)&Ks[(nt * 8 + g8) * 68 + kp];
                unsigned b[2] = {ub.x, ub.y};
                mma8(s[nt], a, b);
            }
        }

        // bias + online softmax (2 rows/lane; 4 lanes/row: xor 1,2)
#pragma unroll
        for (int rid = 0; rid < 2; rid++) {
            const int rloc = m0 + g8 + rid * 8;
            const int rg = tq0 + rloc;
            float vals[16];
            float mx = -1e30f;
#pragma unroll
            for (int nt = 0; nt < 8; nt++) {
#pragma unroll
                for (int cc = 0; cc < 2; cc++) {
                    const int sg = s0 + nt * 8 + 2 * q4 + cc;
                    int delta = min(max(sg - rg, -16), 16) + 16;
                    float v = s[nt][rid * 2 + cc] + qrs[rloc * NREL + delta];
                    vals[nt * 2 + cc] = v;
                    mx = fmaxf(mx, v);
                }
            }
            mx = fmaxf(mx, __shfl_xor_sync(0xffffffffu, mx, 1));
            mx = fmaxf(mx, __shfl_xor_sync(0xffffffffu, mx, 2));
            const float mnew = fmaxf(mrow[rid], mx);
            const float alpha = __expf(mrow[rid] - mnew);
            float rs = 0.0f;
#pragma unroll
            for (int j = 0; j < 16; j++) {
                vals[j] = __expf(vals[j] - mnew);
                rs += vals[j];
            }
            rs += __shfl_xor_sync(0xffffffffu, rs, 1);
            rs += __shfl_xor_sync(0xffffffffu, rs, 2);
            lrow[rid] = lrow[rid] * alpha + rs;
            mrow[rid] = mnew;
#pragma unroll
            for (int nt = 0; nt < 8; nt++) {
                o[nt][rid * 2]     *= alpha;
                o[nt][rid * 2 + 1] *= alpha;
            }
            // stage P at perm'd columns: pos(2q)=((q&1)<<2)|(q>>1), pos+2 = 2q+1
            const int pc = ((q4 & 1) << 2) | (q4 >> 1);
#pragma unroll
            for (int nt = 0; nt < 8; nt++) {
                Ps[rloc * 68 + nt * 8 + pc]     = f2tf(vals[nt * 2]);
                Ps[rloc * 68 + nt * 8 + pc + 2] = f2tf(vals[nt * 2 + 1]);
            }
        }
        __syncwarp();   // P produced/consumed within this warp only

        // O += P @ V   (Vs rows = d, cols = perm'd s -> same form as Ks)
#pragma unroll
        for (int ks = 0; ks < 8; ks++) {
            const int kp = ks * 8 + q4 * 2;
            unsigned a[4];
            const int mr = m0 + g8;
            uint2 u0 = *(const uint2*)&Ps[mr * 68 + kp];
            uint2 u1 = *(const uint2*)&Ps[(mr + 8) * 68 + kp];
            a[0] = u0.x; a[1] = u1.x; a[2] = u0.y; a[3] = u1.y;
#pragma unroll
            for (int nt = 0; nt < 8; nt++) {
                uint2 ub = *(const uint2*)&Vs[(nt * 8 + g8) * 68 + kp];
                unsigned b[2] = {ub.x, ub.y};
                mma8(o[nt], a, b);
            }
        }
        __syncthreads();   // done reading Ks/Vs; safe to overwrite next iter
    }

    // write attn (tf32 bits) at perm'd e for the out-projection GEMM
    const int b = bh >> 4, h = bh & 15;
    const int pc = ((q4 & 1) << 2) | (q4 >> 1);
#pragma unroll
    for (int rid = 0; rid < 2; rid++) {
        const int t = tq0 + m0 + g8 + rid * 8;
        const float inv = 1.0f / lrow[rid];
        float* dst = &g_attn[(size_t)(t * BATCH + b) * EMB + h * HD];
#pragma unroll
        for (int nt = 0; nt < 8; nt++) {
            dst[nt * 8 + pc]     = __uint_as_float(f2tf(o[nt][rid * 2] * inv));
            dst[nt * 8 + pc + 2] = __uint_as_float(f2tf(o[nt][rid * 2 + 1] * inv));
        }
    }
}

// ---------------------------------------------------------------------------
extern "C" void kernel_launch(void* const* d_in, const int* in_sizes, int n_in,
                              void* d_out, int out_size)
{
    (void)in_sizes; (void)n_in; (void)out_size;
    const float* query = (const float*)d_in[0];   // [T,B,E]
    const float* w_in  = (const float*)d_in[1];   // [3E,E]
    const float* b_in  = (const float*)d_in[2];   // [3E]
    const float* relk  = (const float*)d_in[3];   // [33,E]
    const float* w_out = (const float*)d_in[4];   // [E,E]
    const float* b_out = (const float*)d_in[5];   // [E]
    float* out = (float*)d_out;                   // [T,B,E]

    float *qin, *win, *wout, *attn_ptr;
    cudaGetSymbolAddress((void**)&qin,  g_qin);
    cudaGetSymbolAddress((void**)&win,  g_win);
    cudaGetSymbolAddress((void**)&wout, g_wout);
    cudaGetSymbolAddress((void**)&attn_ptr, g_attn);

    // 0) one-time tf32 + k-perm pre-conversion
    cvt_tf32p<<<2048, 256>>>(query, qin, 4096 * 1024 / 8);
    cvt_tf32p<<<1536, 256>>>(w_in,  win, 3072 * 1024 / 8);
    cvt_tf32p<<<512,  256>>>(w_out, wout, 1024 * 1024 / 8);

    const size_t gemm_smem = (size_t)4 * GSTG * sizeof(unsigned);  // 73728 B
    cudaFuncSetAttribute(gemm_tc,
                         cudaFuncAttributeMaxDynamicSharedMemorySize,
                         (int)gemm_smem);

    // 1) fused QKV projection -> tf32 head-major q/k/v (v transposed)
    gemm_tc<<<dim3(24, 32), 256, gemm_smem>>>(
        qin, win, b_in, nullptr, 4096, 3072, 1024, 0);

    // 2) flash attention with relative bias
    const size_t attn_smem =
        (size_t)(4 * 64 * 68 + 33 * 68 + 64 * NREL) * sizeof(float);  // 86032 B
    cudaFuncSetAttribute(attn_tc,
                         cudaFuncAttributeMaxDynamicSharedMemorySize,
                         (int)attn_smem);
    attn_tc<<<dim3(16, 64), 128, attn_smem>>>(relk);

    // 3) output projection (writes fp32 final output)
    gemm_tc<<<dim3(8, 32), 256, gemm_smem>>>(
        attn_ptr, wout, b_out, out, 4096, 1024, 1024, 1);
}

// round 6
// speedup vs baseline: 1.4079x; 1.4079x over previous
#include <cuda_runtime.h>

#define T_LEN 1024
#define BATCH 4
#define EMB   1024
#define NH    16
#define HD    64
#define BH    (BATCH*NH)   // 64
#define NREL  33           // 2L+1

// Scratch (static device arrays: allocation-free per harness rules)
__device__ float g_q[BH * T_LEN * HD];        // tf32 bits, pre-scaled by 0.125
__device__ float g_k[BH * T_LEN * HD];        // tf32 bits
__device__ float g_v[BH * T_LEN * HD];        // tf32 bits
__device__ float g_attn[T_LEN * BATCH * EMB]; // tf32 bits, [t*4+b][e]
__device__ float g_qin[4096 * 1024];          // tf32(query)
__device__ float g_win[3072 * 1024];          // tf32(w_in)
__device__ float g_wout[1024 * 1024];         // tf32(w_out)

__device__ __forceinline__ unsigned f2tf(float f) {
    unsigned u;
    asm("cvt.rna.tf32.f32 %0, %1;" : "=r"(u) : "f"(f));
    return u;
}

// D += A @ B  (m16n8k8, tf32 in, fp32 accum). c aliases d.
__device__ __forceinline__ void mma8(float* c, const unsigned* a, const unsigned* b) {
    asm volatile(
        "mma.sync.aligned.m16n8k8.row.col.f32.tf32.tf32.f32 "
        "{%0,%1,%2,%3}, {%4,%5,%6,%7}, {%8,%9}, {%0,%1,%2,%3};\n"
        : "+f"(c[0]), "+f"(c[1]), "+f"(c[2]), "+f"(c[3])
        : "r"(a[0]), "r"(a[1]), "r"(a[2]), "r"(a[3]), "r"(b[0]), "r"(b[1]));
}

__device__ __forceinline__ unsigned smem_u32(const void* p) {
    return (unsigned)__cvta_generic_to_shared(p);
}

// 4x (8x8 b16) tile load; for tf32 this yields one m16k8 A frag (tiles
// ordered m0k0,m8k0,m0k4,m8k4) or two k8n8 B frags (n0k0,n0k4,n8k0,n8k4).
__device__ __forceinline__ void ldsm4(unsigned* d, unsigned addr) {
    asm volatile(
        "ldmatrix.sync.aligned.m8n8.x4.shared.b16 {%0,%1,%2,%3}, [%4];"
        : "=r"(d[0]), "=r"(d[1]), "=r"(d[2]), "=r"(d[3]) : "r"(addr));
}

// ---------------------------------------------------------------------------
// Elementwise fp32 -> tf32(rna) pre-conversion (bits stored in float array).
// ---------------------------------------------------------------------------
__global__ void __launch_bounds__(256)
cvt_tf32(const float* __restrict__ in, float* __restrict__ out_, int n4)
{
    const int i = blockIdx.x * 256 + threadIdx.x;
    if (i < n4) {
        float4 v = ((const float4*)in)[i];
        uint4 u = make_uint4(f2tf(v.x), f2tf(v.y), f2tf(v.z), f2tf(v.w));
        ((uint4*)out_)[i] = u;
    }
}

// ---------------------------------------------------------------------------
// TC GEMM: C[M,N] = A[M,K] * B[N,K]^T + bias[N].  A,B hold tf32 bit patterns.
// mode 0: scatter tf32-rounded q/k/v (q scaled). mode 1: write fp32 Cout.
// Block 128x128, K-chunk 32, 8 warps, 2-stage smem pipeline, 2 CTAs/SM.
// Fragment loads via ldmatrix.x4 (6 per ks-step instead of 24 scalar LDS).
// ---------------------------------------------------------------------------
#define GSTG (128 * 36)

__global__ void __launch_bounds__(256, 2)
gemm_tc(const float* __restrict__ A, const float* __restrict__ B,
        const float* __restrict__ bias, float* __restrict__ Cout,
        int M, int N, int K, int mode)
{
    extern __shared__ unsigned sh[];
    unsigned* As = sh;               // [2][128*36], stride 36 (≡4 mod 32)
    unsigned* Bs = sh + 2 * GSTG;

    const int tid  = threadIdx.x;
    const int lane = tid & 31;
    const int warp = tid >> 5;
    const int wm   = (warp & 3) * 32;
    const int wn   = (warp >> 2) * 64;
    const int row0 = blockIdx.y * 128;
    const int col0 = blockIdx.x * 128;

    const int lr = tid >> 3;            // 0..31
    const int lk = (tid & 7) * 4;       // 0..28

    // ldmatrix lane address bases (bytes, stage 0)
    const int lrow = lane & 7;
    const int lb3  = (lane >> 3) & 1;
    const int lb4  = lane >> 4;
    unsigned aAddr[2], bAddr[4];
#pragma unroll
    for (int mt = 0; mt < 2; mt++)
        aAddr[mt] = smem_u32(&As[(wm + mt * 16 + lrow + lb3 * 8) * 36 + lb4 * 4]);
#pragma unroll
    for (int np = 0; np < 4; np++)
        bAddr[np] = smem_u32(&Bs[(wn + np * 16 + lb4 * 8 + lrow) * 36 + lb3 * 4]);

    float acc[2][8][4];
#pragma unroll
    for (int mt = 0; mt < 2; mt++)
#pragma unroll
        for (int nt = 0; nt < 8; nt++)
#pragma unroll
            for (int f = 0; f < 4; f++) acc[mt][nt][f] = 0.0f;

    const unsigned* aP = (const unsigned*)A + (size_t)row0 * K;
    const unsigned* bP = (const unsigned*)B + (size_t)col0 * K;

    uint4 pa[4], pb[4];
#pragma unroll
    for (int r = 0; r < 4; r++) {
        pa[r] = *(const uint4*)(aP + (size_t)(lr + 32 * r) * K + lk);
        pb[r] = *(const uint4*)(bP + (size_t)(lr + 32 * r) * K + lk);
    }
#pragma unroll
    for (int r = 0; r < 4; r++) {
        *(uint4*)&As[(lr + 32 * r) * 36 + lk] = pa[r];
        *(uint4*)&Bs[(lr + 32 * r) * 36 + lk] = pb[r];
    }
    __syncthreads();

    const int nC = K >> 5;
    for (int c = 0; c < nC; c++) {
        const unsigned soff = (c & 1) * (GSTG * 4);
        unsigned* An = As + ((c & 1) ^ 1) * GSTG;
        unsigned* Bn = Bs + ((c & 1) ^ 1) * GSTG;

        const bool more = (c + 1 < nC);
        if (more) {
            const int ko = (c + 1) * 32 + lk;
#pragma unroll
            for (int r = 0; r < 4; r++) {
                pa[r] = *(const uint4*)(aP + (size_t)(lr + 32 * r) * K + ko);
                pb[r] = *(const uint4*)(bP + (size_t)(lr + 32 * r) * K + ko);
            }
        }

#pragma unroll
        for (int ks = 0; ks < 4; ks++) {
            const unsigned ko = soff + ks * 32;      // 8 dwords per ks
            unsigned a[2][4], bf[4][4];
            ldsm4(a[0], aAddr[0] + ko);
            ldsm4(a[1], aAddr[1] + ko);
#pragma unroll
            for (int np = 0; np < 4; np++) ldsm4(bf[np], bAddr[np] + ko);
#pragma unroll
            for (int np = 0; np < 4; np++) {
                mma8(acc[0][2 * np],     a[0], &bf[np][0]);
                mma8(acc[1][2 * np],     a[1], &bf[np][0]);
                mma8(acc[0][2 * np + 1], a[0], &bf[np][2]);
                mma8(acc[1][2 * np + 1], a[1], &bf[np][2]);
            }
        }

        if (more) {
#pragma unroll
            for (int r = 0; r < 4; r++) {
                *(uint4*)&An[(lr + 32 * r) * 36 + lk] = pa[r];
                *(uint4*)&Bn[(lr + 32 * r) * 36 + lk] = pb[r];
            }
        }
        __syncthreads();
    }

    // epilogue
    const int q4 = lane & 3;
    const int g8 = lane >> 2;
#pragma unroll
    for (int mt = 0; mt < 2; mt++) {
#pragma unroll
        for (int rr = 0; rr < 2; rr++) {
            const int m = row0 + wm + mt * 16 + g8 + rr * 8;
#pragma unroll
            for (int nt = 0; nt < 8; nt++) {
#pragma unroll
                for (int cc = 0; cc < 2; cc++) {
                    const int n = col0 + wn + nt * 8 + 2 * q4 + cc;
                    float v = acc[mt][nt][rr * 2 + cc] + bias[n];
                    if (mode == 0) {
                        const int sec = n >> 10;       // 0=q 1=k 2=v
                        const int e = n & 1023;
                        const int h = e >> 6, d = e & 63;
                        const int t = m >> 2, b = m & 3;
                        const int bh = b * NH + h;
                        const int idx = (bh * T_LEN + t) * HD + d;
                        if (sec == 0)      g_q[idx] = __uint_as_float(f2tf(v * 0.125f));
                        else if (sec == 1) g_k[idx] = __uint_as_float(f2tf(v));
                        else               g_v[idx] = __uint_as_float(f2tf(v));
                    } else {
                        Cout[(size_t)m * N + n] = v;
                    }
                }
            }
        }
    }
}

// ---------------------------------------------------------------------------
// Flash attention with Shaw relative bias, tensor-core QK^T and PV.
// grid = (16 q-tiles of 64, 64 heads), 128 threads (4 warps, 16 q-rows each).
// Q/K/P fragments via ldmatrix; V scalar (orientation unsuited to LDSM).
// ---------------------------------------------------------------------------
__global__ void __launch_bounds__(128)
attn_tc(const float* __restrict__ relk)
{
    extern __shared__ float sm[];
    unsigned* Qs = (unsigned*)sm;             // [64][68] tf32
    unsigned* Ks = Qs + 64 * 68;              // [64][68]
    unsigned* Vs = Ks + 64 * 68;              // [64][68] rows=s, cols=d
    unsigned* Ps = Vs + 64 * 68;              // [64][68]
    float* rels  = (float*)(Ps + 64 * 68);    // [33][68] fp32
    float* qrs   = rels + 33 * 68;            // [64][33] fp32

    const int tid  = threadIdx.x;
    const int lane = tid & 31;
    const int warp = tid >> 5;                // 0..3
    const int q4   = lane & 3;
    const int g8   = lane >> 2;               // 0..7
    const int bh   = blockIdx.y;
    const int tq0  = blockIdx.x * 64;
    const int m0   = warp * 16;

    // ldmatrix lane address bases (bytes)
    const int lrow = lane & 7;
    const int lb3  = (lane >> 3) & 1;
    const int lb4  = lane >> 4;
    const unsigned qAddr = smem_u32(&Qs[(m0 + lrow + lb3 * 8) * 68 + lb4 * 4]);
    const unsigned pAddr = smem_u32(&Ps[(m0 + lrow + lb3 * 8) * 68 + lb4 * 4]);
    unsigned kAddr[4];
#pragma unroll
    for (int np = 0; np < 4; np++)
        kAddr[np] = smem_u32(&Ks[(np * 16 + lb4 * 8 + lrow) * 68 + lb3 * 4]);

    // load Q tile (64x64, already tf32)
    {
        const uint4* qb = (const uint4*)(g_q + (size_t)(bh * T_LEN + tq0) * HD);
#pragma unroll 2
        for (int i = tid; i < 1024; i += 128)
            *(uint4*)&Qs[(i >> 4) * 68 + (i & 15) * 4] = qb[i];
    }
    // relation keys, first 64 channels
    for (int i = tid; i < NREL * 64; i += 128) {
        const int j = i >> 6, d = i & 63;
        rels[j * 68 + d] = relk[j * EMB + d];
    }
    __syncthreads();

    // qr[r][j] = q[r] . rel[j]
    for (int e = tid; e < 64 * NREL; e += 128) {
        const int r = e / NREL, j = e - r * NREL;
        const float* qp = (const float*)&Qs[r * 68];
        const float* rp = &rels[j * 68];
        float s = 0.0f;
#pragma unroll
        for (int d = 0; d < 64; d++) s = fmaf(qp[d], rp[d], s);
        qrs[r * NREL + j] = s;
    }

    const uint4* kbase = (const uint4*)(g_k + (size_t)bh * T_LEN * HD);
    const uint4* vbase = (const uint4*)(g_v + (size_t)bh * T_LEN * HD);

    // prefetch tile 0
    uint4 pk[8], pv[8];
#pragma unroll
    for (int it = 0; it < 8; it++) {
        const int i = tid + 128 * it;
        pk[it] = kbase[i];
        pv[it] = vbase[i];
    }

    float o[8][4];
#pragma unroll
    for (int nt = 0; nt < 8; nt++)
#pragma unroll
        for (int f = 0; f < 4; f++) o[nt][f] = 0.0f;
    float mrow[2] = {-1e30f, -1e30f};
    float lrow_[2] = {0.0f, 0.0f};

    __syncthreads();   // qrs visible

    for (int kt = 0; kt < 16; kt++) {
        const int s0 = kt * 64;

        // store prefetched tile
#pragma unroll
        for (int it = 0; it < 8; it++) {
            const int i = tid + 128 * it;
            const int r = i >> 4, d4 = (i & 15) * 4;
            *(uint4*)&Ks[r * 68 + d4] = pk[it];
            *(uint4*)&Vs[r * 68 + d4] = pv[it];
        }
        __syncthreads();

        // prefetch next tile
        if (kt + 1 < 16) {
            const uint4* kb = kbase + (size_t)(s0 + 64) * (HD / 4);
            const uint4* vb = vbase + (size_t)(s0 + 64) * (HD / 4);
#pragma unroll
            for (int it = 0; it < 8; it++) {
                const int i = tid + 128 * it;
                pk[it] = kb[i];
                pv[it] = vb[i];
            }
        }

        // S = Q @ K^T  (warp's 16 rows x 64 cols) — all via ldmatrix
        float s[8][4];
#pragma unroll
        for (int nt = 0; nt < 8; nt++)
#pragma unroll
            for (int f = 0; f < 4; f++) s[nt][f] = 0.0f;

#pragma unroll
        for (int ks = 0; ks < 8; ks++) {
            const unsigned ko = ks * 32;
            unsigned a[4];
            ldsm4(a, qAddr + ko);
#pragma unroll
            for (int np = 0; np < 4; np++) {
                unsigned bf[4];
                ldsm4(bf, kAddr[np] + ko);
                mma8(s[2 * np],     a, &bf[0]);
                mma8(s[2 * np + 1], a, &bf[2]);
            }
        }

        // bias + online softmax (2 rows/lane; 4 lanes/row: xor 1,2)
#pragma unroll
        for (int rid = 0; rid < 2; rid++) {
            const int rloc = m0 + g8 + rid * 8;
            const int rg = tq0 + rloc;
            float vals[16];
            float mx = -1e30f;
#pragma unroll
            for (int nt = 0; nt < 8; nt++) {
#pragma unroll
                for (int cc = 0; cc < 2; cc++) {
                    const int sg = s0 + nt * 8 + 2 * q4 + cc;
                    int delta = min(max(sg - rg, -16), 16) + 16;
                    float v = s[nt][rid * 2 + cc] + qrs[rloc * NREL + delta];
                    vals[nt * 2 + cc] = v;
                    mx = fmaxf(mx, v);
                }
            }
            mx = fmaxf(mx, __shfl_xor_sync(0xffffffffu, mx, 1));
            mx = fmaxf(mx, __shfl_xor_sync(0xffffffffu, mx, 2));
            const float mnew = fmaxf(mrow[rid], mx);
            const float alpha = __expf(mrow[rid] - mnew);
            float rs = 0.0f;
#pragma unroll
            for (int j = 0; j < 16; j++) {
                vals[j] = __expf(vals[j] - mnew);
                rs += vals[j];
            }
            rs += __shfl_xor_sync(0xffffffffu, rs, 1);
            rs += __shfl_xor_sync(0xffffffffu, rs, 2);
            lrow_[rid] = lrow_[rid] * alpha + rs;
            mrow[rid] = mnew;
#pragma unroll
            for (int nt = 0; nt < 8; nt++) {
                o[nt][rid * 2]     *= alpha;
                o[nt][rid * 2 + 1] *= alpha;
            }
#pragma unroll
            for (int nt = 0; nt < 8; nt++) {
                const int cpos = nt * 8 + 2 * q4;
                uint2 pw = make_uint2(f2tf(vals[nt * 2]), f2tf(vals[nt * 2 + 1]));
                *(uint2*)&Ps[rloc * 68 + cpos] = pw;
            }
        }
        __syncwarp();   // P produced/consumed within this warp only

        // O += P @ V  (P via ldmatrix, V scalar)
#pragma unroll
        for (int ks = 0; ks < 8; ks++) {
            const int kk = ks * 8 + q4;
            unsigned a[4];
            ldsm4(a, pAddr + ks * 32);
#pragma unroll
            for (int nt = 0; nt < 8; nt++) {
                const int n = nt * 8 + g8;
                unsigned b[2];
                b[0] = Vs[kk * 68 + n];
                b[1] = Vs[(kk + 4) * 68 + n];
                mma8(o[nt], a, b);
            }
        }
        __syncthreads();   // done reading Ks/Vs; safe to overwrite next iter
    }

    // write attn (tf32 bits) in [t][b][e] layout
    const int b = bh >> 4, h = bh & 15;
#pragma unroll
    for (int rid = 0; rid < 2; rid++) {
        const int t = tq0 + m0 + g8 + rid * 8;
        const float inv = 1.0f / lrow_[rid];
#pragma unroll
        for (int nt = 0; nt < 8; nt++) {
            const int d = nt * 8 + 2 * q4;
            uint2 w = make_uint2(f2tf(o[nt][rid * 2] * inv),
                                 f2tf(o[nt][rid * 2 + 1] * inv));
            *(uint2*)&g_attn[(t * BATCH + b) * EMB + h * HD + d] = w;
        }
    }
}

// ---------------------------------------------------------------------------
extern "C" void kernel_launch(void* const* d_in, const int* in_sizes, int n_in,
                              void* d_out, int out_size)
{
    (void)in_sizes; (void)n_in; (void)out_size;
    const float* query = (const float*)d_in[0];   // [T,B,E]
    const float* w_in  = (const float*)d_in[1];   // [3E,E]
    const float* b_in  = (const float*)d_in[2];   // [3E]
    const float* relk  = (const float*)d_in[3];   // [33,E]
    const float* w_out = (const float*)d_in[4];   // [E,E]
    const float* b_out = (const float*)d_in[5];   // [E]
    float* out = (float*)d_out;                   // [T,B,E]

    float *qin, *win, *wout, *attn_ptr;
    cudaGetSymbolAddress((void**)&qin,  g_qin);
    cudaGetSymbolAddress((void**)&win,  g_win);
    cudaGetSymbolAddress((void**)&wout, g_wout);
    cudaGetSymbolAddress((void**)&attn_ptr, g_attn);

    // 0) one-time tf32 pre-conversion of fp32 operands
    cvt_tf32<<<4096, 256>>>(query, qin, 4096 * 1024 / 4);
    cvt_tf32<<<3072, 256>>>(w_in,  win, 3072 * 1024 / 4);
    cvt_tf32<<<1024, 256>>>(w_out, wout, 1024 * 1024 / 4);

    const size_t gemm_smem = (size_t)4 * GSTG * sizeof(unsigned);  // 73728 B
    cudaFuncSetAttribute(gemm_tc,
                         cudaFuncAttributeMaxDynamicSharedMemorySize,
                         (int)gemm_smem);

    // 1) fused QKV projection -> tf32 head-major q/k/v
    gemm_tc<<<dim3(24, 32), 256, gemm_smem>>>(
        qin, win, b_in, nullptr, 4096, 3072, 1024, 0);

    // 2) flash attention with relative bias
    const size_t attn_smem =
        (size_t)(4 * 64 * 68 + 33 * 68 + 64 * NREL) * sizeof(float);  // 87056 B
    cudaFuncSetAttribute(attn_tc,
                         cudaFuncAttributeMaxDynamicSharedMemorySize,
                         (int)attn_smem);
    attn_tc<<<dim3(16, 64), 128, attn_smem>>>(relk);

    // 3) output projection (writes fp32 final output)
    gemm_tc<<<dim3(8, 32), 256, gemm_smem>>>(
        attn_ptr, wout, b_out, out, 4096, 1024, 1024, 1);
}

// round 7
// speedup vs baseline: 1.5066x; 1.0701x over previous
#include <cuda_runtime.h>

#define T_LEN 1024
#define BATCH 4
#define EMB   1024
#define NH    16
#define HD    64
#define BH    (BATCH*NH)   // 64
#define NREL  33           // 2L+1

// Scratch (static device arrays: allocation-free per harness rules)
__device__ float g_q[BH * T_LEN * HD];        // tf32 bits, pre-scaled by 0.125
__device__ float g_k[BH * T_LEN * HD];        // tf32 bits
__device__ float g_v[BH * HD * T_LEN];        // tf32 bits, TRANSPOSED [bh][d][t]
__device__ float g_attn[T_LEN * BATCH * EMB]; // tf32 bits, [t*4+b][e]
__device__ float g_qin[4096 * 1024];          // tf32(query)
__device__ float g_win[3072 * 1024];          // tf32(w_in)
__device__ float g_wout[1024 * 1024];         // tf32(w_out)

__device__ __forceinline__ unsigned f2tf(float f) {
    unsigned u;
    asm("cvt.rna.tf32.f32 %0, %1;" : "=r"(u) : "f"(f));
    return u;
}

// D += A @ B  (m16n8k8, tf32 in, fp32 accum). c aliases d.
__device__ __forceinline__ void mma8(float* c, const unsigned* a, const unsigned* b) {
    asm volatile(
        "mma.sync.aligned.m16n8k8.row.col.f32.tf32.tf32.f32 "
        "{%0,%1,%2,%3}, {%4,%5,%6,%7}, {%8,%9}, {%0,%1,%2,%3};\n"
        : "+f"(c[0]), "+f"(c[1]), "+f"(c[2]), "+f"(c[3])
        : "r"(a[0]), "r"(a[1]), "r"(a[2]), "r"(a[3]), "r"(b[0]), "r"(b[1]));
}

__device__ __forceinline__ unsigned smem_u32(const void* p) {
    return (unsigned)__cvta_generic_to_shared(p);
}

// 4x (8x8 b16) tile load; for tf32 this yields one m16k8 A frag (tiles
// ordered m0k0,m8k0,m0k4,m8k4) or two k8n8 B frags (n0k0,n0k4,n8k0,n8k4).
__device__ __forceinline__ void ldsm4(unsigned* d, unsigned addr) {
    asm volatile(
        "ldmatrix.sync.aligned.m8n8.x4.shared.b16 {%0,%1,%2,%3}, [%4];"
        : "=r"(d[0]), "=r"(d[1]), "=r"(d[2]), "=r"(d[3]) : "r"(addr));
}

// ---------------------------------------------------------------------------
// Elementwise fp32 -> tf32(rna) pre-conversion (bits stored in float array).
// ---------------------------------------------------------------------------
__global__ void __launch_bounds__(256)
cvt_tf32(const float* __restrict__ in, float* __restrict__ out_, int n4)
{
    const int i = blockIdx.x * 256 + threadIdx.x;
    if (i < n4) {
        float4 v = ((const float4*)in)[i];
        uint4 u = make_uint4(f2tf(v.x), f2tf(v.y), f2tf(v.z), f2tf(v.w));
        ((uint4*)out_)[i] = u;
    }
}

// ---------------------------------------------------------------------------
// TC GEMM: C[M,N] = A[M,K] * B[N,K]^T + bias[N].  A,B hold tf32 bit patterns.
// mode 0: scatter tf32-rounded q/k/v (q scaled, V TRANSPOSED). mode 1: Cout.
// Block 128x128, K-chunk 32, 8 warps, 2-stage smem pipeline, 2 CTAs/SM.
// Fragment loads via ldmatrix.x4.
// ---------------------------------------------------------------------------
#define GSTG (128 * 36)

__global__ void __launch_bounds__(256, 2)
gemm_tc(const float* __restrict__ A, const float* __restrict__ B,
        const float* __restrict__ bias, float* __restrict__ Cout,
        int M, int N, int K, int mode)
{
    extern __shared__ unsigned sh[];
    unsigned* As = sh;               // [2][128*36], stride 36 (≡4 mod 32)
    unsigned* Bs = sh + 2 * GSTG;

    const int tid  = threadIdx.x;
    const int lane = tid & 31;
    const int warp = tid >> 5;
    const int wm   = (warp & 3) * 32;
    const int wn   = (warp >> 2) * 64;
    const int row0 = blockIdx.y * 128;
    const int col0 = blockIdx.x * 128;

    const int lr = tid >> 3;            // 0..31
    const int lk = (tid & 7) * 4;       // 0..28

    // ldmatrix lane address bases (bytes, stage 0)
    const int lrow = lane & 7;
    const int lb3  = (lane >> 3) & 1;
    const int lb4  = lane >> 4;
    unsigned aAddr[2], bAddr[4];
#pragma unroll
    for (int mt = 0; mt < 2; mt++)
        aAddr[mt] = smem_u32(&As[(wm + mt * 16 + lrow + lb3 * 8) * 36 + lb4 * 4]);
#pragma unroll
    for (int np = 0; np < 4; np++)
        bAddr[np] = smem_u32(&Bs[(wn + np * 16 + lb4 * 8 + lrow) * 36 + lb3 * 4]);

    float acc[2][8][4];
#pragma unroll
    for (int mt = 0; mt < 2; mt++)
#pragma unroll
        for (int nt = 0; nt < 8; nt++)
#pragma unroll
            for (int f = 0; f < 4; f++) acc[mt][nt][f] = 0.0f;

    const unsigned* aP = (const unsigned*)A + (size_t)row0 * K;
    const unsigned* bP = (const unsigned*)B + (size_t)col0 * K;

    uint4 pa[4], pb[4];
#pragma unroll
    for (int r = 0; r < 4; r++) {
        pa[r] = *(const uint4*)(aP + (size_t)(lr + 32 * r) * K + lk);
        pb[r] = *(const uint4*)(bP + (size_t)(lr + 32 * r) * K + lk);
    }
#pragma unroll
    for (int r = 0; r < 4; r++) {
        *(uint4*)&As[(lr + 32 * r) * 36 + lk] = pa[r];
        *(uint4*)&Bs[(lr + 32 * r) * 36 + lk] = pb[r];
    }
    __syncthreads();

    const int nC = K >> 5;
    for (int c = 0; c < nC; c++) {
        const unsigned soff = (c & 1) * (GSTG * 4);
        unsigned* An = As + ((c & 1) ^ 1) * GSTG;
        unsigned* Bn = Bs + ((c & 1) ^ 1) * GSTG;

        const bool more = (c + 1 < nC);
        if (more) {
            const int ko = (c + 1) * 32 + lk;
#pragma unroll
            for (int r = 0; r < 4; r++) {
                pa[r] = *(const uint4*)(aP + (size_t)(lr + 32 * r) * K + ko);
                pb[r] = *(const uint4*)(bP + (size_t)(lr + 32 * r) * K + ko);
            }
        }

#pragma unroll
        for (int ks = 0; ks < 4; ks++) {
            const unsigned ko = soff + ks * 32;      // 8 dwords per ks
            unsigned a[2][4], bf[4][4];
            ldsm4(a[0], aAddr[0] + ko);
            ldsm4(a[1], aAddr[1] + ko);
#pragma unroll
            for (int np = 0; np < 4; np++) ldsm4(bf[np], bAddr[np] + ko);
#pragma unroll
            for (int np = 0; np < 4; np++) {
                mma8(acc[0][2 * np],     a[0], &bf[np][0]);
                mma8(acc[1][2 * np],     a[1], &bf[np][0]);
                mma8(acc[0][2 * np + 1], a[0], &bf[np][2]);
                mma8(acc[1][2 * np + 1], a[1], &bf[np][2]);
            }
        }

        if (more) {
#pragma unroll
            for (int r = 0; r < 4; r++) {
                *(uint4*)&An[(lr + 32 * r) * 36 + lk] = pa[r];
                *(uint4*)&Bn[(lr + 32 * r) * 36 + lk] = pb[r];
            }
        }
        __syncthreads();
    }

    // epilogue
    const int q4 = lane & 3;
    const int g8 = lane >> 2;
#pragma unroll
    for (int mt = 0; mt < 2; mt++) {
#pragma unroll
        for (int rr = 0; rr < 2; rr++) {
            const int m = row0 + wm + mt * 16 + g8 + rr * 8;
#pragma unroll
            for (int nt = 0; nt < 8; nt++) {
#pragma unroll
                for (int cc = 0; cc < 2; cc++) {
                    const int n = col0 + wn + nt * 8 + 2 * q4 + cc;
                    float v = acc[mt][nt][rr * 2 + cc] + bias[n];
                    if (mode == 0) {
                        const int sec = n >> 10;       // 0=q 1=k 2=v
                        const int e = n & 1023;
                        const int h = e >> 6, d = e & 63;
                        const int t = m >> 2, b = m & 3;
                        const int bh = b * NH + h;
                        if (sec == 0)
                            g_q[(bh * T_LEN + t) * HD + d] =
                                __uint_as_float(f2tf(v * 0.125f));
                        else if (sec == 1)
                            g_k[(bh * T_LEN + t) * HD + d] =
                                __uint_as_float(f2tf(v));
                        else  // V transposed: [bh][d][t]
                            g_v[((size_t)bh * HD + d) * T_LEN + t] =
                                __uint_as_float(f2tf(v));
                    } else {
                        Cout[(size_t)m * N + n] = v;
                    }
                }
            }
        }
    }
}

// ---------------------------------------------------------------------------
// Flash attention with Shaw relative bias, tensor-core QK^T and PV.
// grid = (16 q-tiles of 64, 64 heads), 128 threads (4 warps, 16 q-rows each).
// ALL fragments (Q/K/P/V) via ldmatrix — V is pre-transposed in global.
// ---------------------------------------------------------------------------
__global__ void __launch_bounds__(128)
attn_tc(const float* __restrict__ relk)
{
    extern __shared__ float sm[];
    unsigned* Qs = (unsigned*)sm;             // [64][68] tf32  rows=t, cols=d
    unsigned* Ks = Qs + 64 * 68;              // [64][68]       rows=s, cols=d
    unsigned* Vs = Ks + 64 * 68;              // [64][68]       rows=d, cols=s
    unsigned* Ps = Vs + 64 * 68;              // [64][68]       rows=t, cols=s
    float* rels  = (float*)(Ps + 64 * 68);    // [33][68] fp32
    float* qrs   = rels + 33 * 68;            // [64][33] fp32

    const int tid  = threadIdx.x;
    const int lane = tid & 31;
    const int warp = tid >> 5;                // 0..3
    const int q4   = lane & 3;
    const int g8   = lane >> 2;               // 0..7
    const int bh   = blockIdx.y;
    const int tq0  = blockIdx.x * 64;
    const int m0   = warp * 16;

    // ldmatrix lane address bases (bytes)
    const int lrow = lane & 7;
    const int lb3  = (lane >> 3) & 1;
    const int lb4  = lane >> 4;
    const unsigned qAddr = smem_u32(&Qs[(m0 + lrow + lb3 * 8) * 68 + lb4 * 4]);
    const unsigned pAddr = smem_u32(&Ps[(m0 + lrow + lb3 * 8) * 68 + lb4 * 4]);
    unsigned kAddr[4], vAddr[4];
#pragma unroll
    for (int np = 0; np < 4; np++) {
        kAddr[np] = smem_u32(&Ks[(np * 16 + lb4 * 8 + lrow) * 68 + lb3 * 4]);
        vAddr[np] = smem_u32(&Vs[(np * 16 + lb4 * 8 + lrow) * 68 + lb3 * 4]);
    }

    // load Q tile (64x64, already tf32)
    {
        const uint4* qb = (const uint4*)(g_q + (size_t)(bh * T_LEN + tq0) * HD);
#pragma unroll 2
        for (int i = tid; i < 1024; i += 128)
            *(uint4*)&Qs[(i >> 4) * 68 + (i & 15) * 4] = qb[i];
    }
    // relation keys, first 64 channels
    for (int i = tid; i < NREL * 64; i += 128) {
        const int j = i >> 6, d = i & 63;
        rels[j * 68 + d] = relk[j * EMB + d];
    }
    __syncthreads();

    // qr[r][j] = q[r] . rel[j]
    for (int e = tid; e < 64 * NREL; e += 128) {
        const int r = e / NREL, j = e - r * NREL;
        const float* qp = (const float*)&Qs[r * 68];
        const float* rp = &rels[j * 68];
        float s = 0.0f;
#pragma unroll
        for (int d = 0; d < 64; d++) s = fmaf(qp[d], rp[d], s);
        qrs[r * NREL + j] = s;
    }

    const uint4* kbase = (const uint4*)(g_k + (size_t)bh * T_LEN * HD);
    const float* vbase = g_v + (size_t)bh * HD * T_LEN;   // [d][t]

    // prefetch tile 0
    uint4 pk[8], pv[8];
#pragma unroll
    for (int it = 0; it < 8; it++) {
        const int i = tid + 128 * it;
        const int r = i >> 4, c4 = (i & 15) * 4;
        pk[it] = kbase[i];
        pv[it] = *(const uint4*)(vbase + (size_t)r * T_LEN + c4);
    }

    float o[8][4];
#pragma unroll
    for (int nt = 0; nt < 8; nt++)
#pragma unroll
        for (int f = 0; f < 4; f++) o[nt][f] = 0.0f;
    float mrow[2] = {-1e30f, -1e30f};
    float lrow_[2] = {0.0f, 0.0f};

    __syncthreads();   // qrs visible

    for (int kt = 0; kt < 16; kt++) {
        const int s0 = kt * 64;

        // store prefetched tile: Ks rows=s cols=d; Vs rows=d cols=s
#pragma unroll
        for (int it = 0; it < 8; it++) {
            const int i = tid + 128 * it;
            const int r = i >> 4, c4 = (i & 15) * 4;
            *(uint4*)&Ks[r * 68 + c4] = pk[it];
            *(uint4*)&Vs[r * 68 + c4] = pv[it];
        }
        __syncthreads();

        // prefetch next tile
        if (kt + 1 < 16) {
            const uint4* kb = kbase + (size_t)(s0 + 64) * (HD / 4);
#pragma unroll
            for (int it = 0; it < 8; it++) {
                const int i = tid + 128 * it;
                const int r = i >> 4, c4 = (i & 15) * 4;
                pk[it] = kb[i];
                pv[it] = *(const uint4*)(vbase + (size_t)r * T_LEN + s0 + 64 + c4);
            }
        }

        // S = Q @ K^T  (warp's 16 rows x 64 cols) — all via ldmatrix
        float s[8][4];
#pragma unroll
        for (int nt = 0; nt < 8; nt++)
#pragma unroll
            for (int f = 0; f < 4; f++) s[nt][f] = 0.0f;

#pragma unroll
        for (int ks = 0; ks < 8; ks++) {
            const unsigned ko = ks * 32;
            unsigned a[4];
            ldsm4(a, qAddr + ko);
#pragma unroll
            for (int np = 0; np < 4; np++) {
                unsigned bf[4];
                ldsm4(bf, kAddr[np] + ko);
                mma8(s[2 * np],     a, &bf[0]);
                mma8(s[2 * np + 1], a, &bf[2]);
            }
        }

        // bias + online softmax (2 rows/lane; 4 lanes/row: xor 1,2)
#pragma unroll
        for (int rid = 0; rid < 2; rid++) {
            const int rloc = m0 + g8 + rid * 8;
            const int rg = tq0 + rloc;
            float vals[16];
            float mx = -1e30f;
#pragma unroll
            for (int nt = 0; nt < 8; nt++) {
#pragma unroll
                for (int cc = 0; cc < 2; cc++) {
                    const int sg = s0 + nt * 8 + 2 * q4 + cc;
                    int delta = min(max(sg - rg, -16), 16) + 16;
                    float v = s[nt][rid * 2 + cc] + qrs[rloc * NREL + delta];
                    vals[nt * 2 + cc] = v;
                    mx = fmaxf(mx, v);
                }
            }
            mx = fmaxf(mx, __shfl_xor_sync(0xffffffffu, mx, 1));
            mx = fmaxf(mx, __shfl_xor_sync(0xffffffffu, mx, 2));
            const float mnew = fmaxf(mrow[rid], mx);
            const float alpha = __expf(mrow[rid] - mnew);
            float rs = 0.0f;
#pragma unroll
            for (int j = 0; j < 16; j++) {
                vals[j] = __expf(vals[j] - mnew);
                rs += vals[j];
            }
            rs += __shfl_xor_sync(0xffffffffu, rs, 1);
            rs += __shfl_xor_sync(0xffffffffu, rs, 2);
            lrow_[rid] = lrow_[rid] * alpha + rs;
            mrow[rid] = mnew;
#pragma unroll
            for (int nt = 0; nt < 8; nt++) {
                o[nt][rid * 2]     *= alpha;
                o[nt][rid * 2 + 1] *= alpha;
            }
#pragma unroll
            for (int nt = 0; nt < 8; nt++) {
                const int cpos = nt * 8 + 2 * q4;
                uint2 pw = make_uint2(f2tf(vals[nt * 2]), f2tf(vals[nt * 2 + 1]));
                *(uint2*)&Ps[rloc * 68 + cpos] = pw;
            }
        }
        __syncwarp();   // P produced/consumed within this warp only

        // O += P @ V  (P and V via ldmatrix; Vs rows=d(n), cols=s(k))
#pragma unroll
        for (int ks = 0; ks < 8; ks++) {
            const unsigned ko = ks * 32;
            unsigned a[4];
            ldsm4(a, pAddr + ko);
#pragma unroll
            for (int np = 0; np < 4; np++) {
                unsigned vf[4];
                ldsm4(vf, vAddr[np] + ko);
                mma8(o[2 * np],     a, &vf[0]);
                mma8(o[2 * np + 1], a, &vf[2]);
            }
        }
        __syncthreads();   // done reading Ks/Vs; safe to overwrite next iter
    }

    // write attn (tf32 bits) in [t][b][e] layout
    const int b = bh >> 4, h = bh & 15;
#pragma unroll
    for (int rid = 0; rid < 2; rid++) {
        const int t = tq0 + m0 + g8 + rid * 8;
        const float inv = 1.0f / lrow_[rid];
#pragma unroll
        for (int nt = 0; nt < 8; nt++) {
            const int d = nt * 8 + 2 * q4;
            uint2 w = make_uint2(f2tf(o[nt][rid * 2] * inv),
                                 f2tf(o[nt][rid * 2 + 1] * inv));
            *(uint2*)&g_attn[(t * BATCH + b) * EMB + h * HD + d] = w;
        }
    }
}

// ---------------------------------------------------------------------------
extern "C" void kernel_launch(void* const* d_in, const int* in_sizes, int n_in,
                              void* d_out, int out_size)
{
    (void)in_sizes; (void)n_in; (void)out_size;
    const float* query = (const float*)d_in[0];   // [T,B,E]
    const float* w_in  = (const float*)d_in[1];   // [3E,E]
    const float* b_in  = (const float*)d_in[2];   // [3E]
    const float* relk  = (const float*)d_in[3];   // [33,E]
    const float* w_out = (const float*)d_in[4];   // [E,E]
    const float* b_out = (const float*)d_in[5];   // [E]
    float* out = (float*)d_out;                   // [T,B,E]

    float *qin, *win, *wout, *attn_ptr;
    cudaGetSymbolAddress((void**)&qin,  g_qin);
    cudaGetSymbolAddress((void**)&win,  g_win);
    cudaGetSymbolAddress((void**)&wout, g_wout);
    cudaGetSymbolAddress((void**)&attn_ptr, g_attn);

    // 0) one-time tf32 pre-conversion of fp32 operands
    cvt_tf32<<<4096, 256>>>(query, qin, 4096 * 1024 / 4);
    cvt_tf32<<<3072, 256>>>(w_in,  win, 3072 * 1024 / 4);
    cvt_tf32<<<1024, 256>>>(w_out, wout, 1024 * 1024 / 4);

    const size_t gemm_smem = (size_t)4 * GSTG * sizeof(unsigned);  // 73728 B
    cudaFuncSetAttribute(gemm_tc,
                         cudaFuncAttributeMaxDynamicSharedMemorySize,
                         (int)gemm_smem);

    // 1) fused QKV projection -> tf32 head-major q/k/v (V transposed)
    gemm_tc<<<dim3(24, 32), 256, gemm_smem>>>(
        qin, win, b_in, nullptr, 4096, 3072, 1024, 0);

    // 2) flash attention with relative bias
    const size_t attn_smem =
        (size_t)(4 * 64 * 68 + 33 * 68 + 64 * NREL) * sizeof(float);  // 87056 B
    cudaFuncSetAttribute(attn_tc,
                         cudaFuncAttributeMaxDynamicSharedMemorySize,
                         (int)attn_smem);
    attn_tc<<<dim3(16, 64), 128, attn_smem>>>(relk);

    // 3) output projection (writes fp32 final output)
    gemm_tc<<<dim3(8, 32), 256, gemm_smem>>>(
        attn_ptr, wout, b_out, out, 4096, 1024, 1024, 1);
}